// round 8
// baseline (speedup 1.0000x reference)
#include <cuda_runtime.h>

#define NSEQ 12800
#define TSTEPS 512
#define CHUNK_T 8
#define NCHUNK (TSTEPS / CHUNK_T)

typedef unsigned long long u64;

// ---------- packed f32x2 + fast-math helpers ----------
__device__ __forceinline__ u64 pk2(float lo, float hi) {
    u64 u; asm("mov.b64 %0, {%1,%2};" : "=l"(u) : "f"(lo), "f"(hi)); return u;
}
__device__ __forceinline__ float2 upk2(u64 u) {
    float2 v; asm("mov.b64 {%0,%1}, %2;" : "=f"(v.x), "=f"(v.y) : "l"(u)); return v;
}
__device__ __forceinline__ u64 ffma2(u64 a, u64 b, u64 c) {
    u64 d; asm("fma.rn.f32x2 %0, %1, %2, %3;" : "=l"(d) : "l"(a), "l"(b), "l"(c)); return d;
}
__device__ __forceinline__ float tanh_a(float x) {
    float r; asm("tanh.approx.f32 %0, %1;" : "=f"(r) : "f"(x)); return r;
}
__device__ __forceinline__ float hsum(u64 a) { float2 v = upk2(a); return v.x + v.y; }

// r/z gate weights pre-scaled by 0.5: sigmoid(x) = 0.5*tanh(x/2) + 0.5  (1 MUFU)
#define KRZ (0.5f)

// ---------- global scratch: ping-pong activation buffers, layout (T, N, 16) ----------
__device__ float g_bufA[(size_t)TSTEPS * NSEQ * 16];
__device__ float g_bufB[(size_t)TSTEPS * NSEQ * 16];

// ---------- per-WARP cp.async chunk loader (no block barriers anywhere) ----------
// warp-private chunk layout: [tt (CHUNK_T)][scan (4)][INF floats + 16B pad]
template <int INF, bool RAW>
__device__ __forceinline__ void issue_chunk_w(char* dst, const float* __restrict__ x_in,
                                              int n0, int c, int dir, int lane) {
    constexpr int VPS = INF / 4;                 // 16B vectors per scan row
    constexpr int ROW_B = INF * 4 + 16;
    constexpr int TT_B = 4 * ROW_B;
    constexpr int PER_TT = 4 * VPS;
    constexpr int TOTAL = CHUNK_T * PER_TT;      // 128 (INF=16) / 64 (INF=8)
#pragma unroll
    for (int k = 0; k < TOTAL / 32; k++) {
        int j = k * 32 + lane;
        int tt = j / PER_TT;
        int r = j % PER_TT;
        int scan = r / VPS;
        int c16 = r % VPS;
        int t = dir ? (TSTEPS - 1 - (c * CHUNK_T + tt)) : (c * CHUNK_T + tt);
        const float* g = RAW
            ? x_in + (size_t)(n0 + scan) * 4096 + (size_t)t * 8 + c16 * 4
            : x_in + ((size_t)t * NSEQ + (size_t)(n0 + scan)) * 16 + c16 * 4;
        unsigned s = (unsigned)__cvta_generic_to_shared(dst + tt * TT_B + scan * ROW_B + c16 * 16);
        asm volatile("cp.async.cg.shared.global [%0], [%1], 16;" :: "r"(s), "l"(g));
    }
}

// One bidirectional-GRU layer. Each WARP owns 4 scans of one direction and
// free-runs: private double-buffered cp.async x-ring, no __syncthreads.
// 8 lanes per scan; lane u owns hidden unit u (gate rows u, u+8, u+16).
// h broadcast via parity-double-buffered smem exchange (STS + syncwarp +
// 2x LDS.128 broadcast) instead of 8 SHFLs. All weights in registers.
// HEAD (layer 3): fwd only, no stores; fused 1-step bwd GRU at t=T-1 (h0=0)
// + lin1/LeakyReLU(0.2)/lin2 head.
template <int INF, bool RAW_IN, bool HEAD>
__global__ void __launch_bounds__(128, 4)
gru_layer_kernel(const float* __restrict__ x_in, float* __restrict__ x_out,
                 const float* __restrict__ Wih, const float* __restrict__ Whh,
                 const float* __restrict__ bih, const float* __restrict__ bhh,
                 int wih_stride,
                 const float* __restrict__ l1w, const float* __restrict__ l1b,
                 const float* __restrict__ l2w, const float* __restrict__ l2b,
                 float* __restrict__ out)
{
    constexpr int IN_PAIRS = INF / 2;
    constexpr int ROW_B = INF * 4 + 16;
    constexpr int TT_B = 4 * ROW_B;
    constexpr int CHUNK_B = CHUNK_T * TT_B;
    constexpr int WARP_B = 2 * CHUNK_B;

    extern __shared__ char sb[];

    const int tid = threadIdx.x;
    const int wid = tid >> 5;
    const int lane = tid & 31;
    const int u = tid & 7;
    const int sg = (tid >> 3) & 3;               // scan within warp
    const int warpG = blockIdx.x * 4 + wid;
    const int dir = HEAD ? 0 : (warpG / (NSEQ / 4));
    const int wi  = HEAD ? warpG : (warpG % (NSEQ / 4));
    const int n0 = wi * 4;
    const int n = n0 + sg;
    char* wsb = sb + wid * WARP_B;               // this warp's private x ring
    // h-exchange: per warp 2 parity buffers x 32 floats
    char* hx = sb + 4 * WARP_B + wid * 256;

    // ---- register weights, pre-scaled ----
    const float* wih = Wih + dir * wih_stride;
    const float* whh = Whh + dir * 192;
    const float* bi  = bih + dir * 24;
    const float* bh  = bhh + dir * 24;

    u64 wr[IN_PAIRS], wz[IN_PAIRS], wn[IN_PAIRS];
#pragma unroll
    for (int p = 0; p < IN_PAIRS; p++) {
        wr[p] = pk2(KRZ * wih[(u     ) * INF + 2 * p], KRZ * wih[(u     ) * INF + 2 * p + 1]);
        wz[p] = pk2(KRZ * wih[(u +  8) * INF + 2 * p], KRZ * wih[(u +  8) * INF + 2 * p + 1]);
        wn[p] = pk2(       wih[(u + 16) * INF + 2 * p],        wih[(u + 16) * INF + 2 * p + 1]);
    }
    u64 ur[4], uz[4], un[4];
#pragma unroll
    for (int p = 0; p < 4; p++) {
        ur[p] = pk2(KRZ * whh[(u     ) * 8 + 2 * p], KRZ * whh[(u     ) * 8 + 2 * p + 1]);
        uz[p] = pk2(KRZ * whh[(u +  8) * 8 + 2 * p], KRZ * whh[(u +  8) * 8 + 2 * p + 1]);
        un[p] = pk2(       whh[(u + 16) * 8 + 2 * p],        whh[(u + 16) * 8 + 2 * p + 1]);
    }
    const u64 brp  = pk2(KRZ * (bi[u]     + bh[u]),     0.0f);
    const u64 bzp  = pk2(KRZ * (bi[u + 8] + bh[u + 8]), 0.0f);
    const u64 bnxp = pk2(bi[u + 16], 0.0f);
    const u64 bnhp = pk2(bh[u + 16], 0.0f);

    const int t0 = dir ? (TSTEPS - 1) : 0;
    float* op = HEAD ? nullptr
                     : (x_out + ((size_t)t0 * NSEQ + (size_t)n) * 16 + dir * 8 + u);
    const ptrdiff_t ostep = (ptrdiff_t)NSEQ * 16 * (dir ? -1 : 1);

    // ---- prime the per-warp pipeline ----
    issue_chunk_w<INF, RAW_IN>(wsb, x_in, n0, 0, dir, lane);
    asm volatile("cp.async.commit_group;" ::: "memory");
    issue_chunk_w<INF, RAW_IN>(wsb + CHUNK_B, x_in, n0, 1, dir, lane);
    asm volatile("cp.async.commit_group;" ::: "memory");

    float h = 0.0f;
    // seed h-exchange buffer 0 with h=0 (visible after first chunk's syncwarp)
    *reinterpret_cast<float*>(hx + lane * 4) = 0.0f;

#pragma unroll 1
    for (int c = 0; c < NCHUNK; c++) {
        asm volatile("cp.async.wait_group 1;" ::: "memory");
        __syncwarp();
        const char* xbase = wsb + (c & 1) * CHUNK_B + sg * ROW_B;

#pragma unroll
        for (int tt = 0; tt < CHUNK_T; tt++) {
            // h[0..7] of this scan: two broadcast LDS.128 from parity buffer tt&1
            const char* hb = hx + (tt & 1) * 128 + sg * 32;
            ulonglong2 hpa = *reinterpret_cast<const ulonglong2*>(hb);
            ulonglong2 hpb = *reinterpret_cast<const ulonglong2*>(hb + 16);

            const ulonglong2* q = reinterpret_cast<const ulonglong2*>(xbase + tt * TT_B);

            u64 ar = brp, az = bzp, axn = bnxp, ahn = bnhp;
            // x-projection in blocks of 4 pairs (fills the LDS latency window)
#pragma unroll
            for (int blk = 0; blk < IN_PAIRS / 4; blk++) {
                ulonglong2 va = q[2 * blk];
                ulonglong2 vb = q[2 * blk + 1];
                ar  = ffma2(wr[4 * blk + 0], va.x, ar);
                az  = ffma2(wz[4 * blk + 0], va.x, az);
                axn = ffma2(wn[4 * blk + 0], va.x, axn);
                ar  = ffma2(wr[4 * blk + 1], va.y, ar);
                az  = ffma2(wz[4 * blk + 1], va.y, az);
                axn = ffma2(wn[4 * blk + 1], va.y, axn);
                ar  = ffma2(wr[4 * blk + 2], vb.x, ar);
                az  = ffma2(wz[4 * blk + 2], vb.x, az);
                axn = ffma2(wn[4 * blk + 2], vb.x, axn);
                ar  = ffma2(wr[4 * blk + 3], vb.y, ar);
                az  = ffma2(wz[4 * blk + 3], vb.y, az);
                axn = ffma2(wn[4 * blk + 3], vb.y, axn);
            }
            // h-recurrence
            ar  = ffma2(ur[0], hpa.x, ar);
            az  = ffma2(uz[0], hpa.x, az);
            ahn = ffma2(un[0], hpa.x, ahn);
            ar  = ffma2(ur[1], hpa.y, ar);
            az  = ffma2(uz[1], hpa.y, az);
            ahn = ffma2(un[1], hpa.y, ahn);
            ar  = ffma2(ur[2], hpb.x, ar);
            az  = ffma2(uz[2], hpb.x, az);
            ahn = ffma2(un[2], hpb.x, ahn);
            ar  = ffma2(ur[3], hpb.y, ar);
            az  = ffma2(uz[3], hpb.y, az);
            ahn = ffma2(un[3], hpb.y, ahn);

            float r = fmaf(0.5f, tanh_a(hsum(ar)), 0.5f);   // sigmoid
            float z = fmaf(0.5f, tanh_a(hsum(az)), 0.5f);   // sigmoid
            float nn = tanh_a(fmaf(r, hsum(ahn), hsum(axn)));
            h = fmaf(z, h - nn, nn);

            // publish h for next step into the other parity buffer
            *reinterpret_cast<float*>(hx + ((tt + 1) & 1) * 128 + lane * 4) = h;
            __syncwarp();

            if (!HEAD) { *op = h; op += ostep; }
        }
        // refill the buffer this warp just finished consuming
        if (c + 2 < NCHUNK)
            issue_chunk_w<INF, RAW_IN>(wsb + (c & 1) * CHUNK_B, x_in, n0, c + 2, dir, lane);
        asm volatile("cp.async.commit_group;" ::: "memory");
    }

    if (HEAD) {
        // x[T-1] still resident in the last chunk's buffer
        const char* xrow = wsb + ((NCHUNK - 1) & 1) * CHUNK_B
                         + sg * ROW_B + (CHUNK_T - 1) * TT_B;
        const ulonglong2* q = reinterpret_cast<const ulonglong2*>(xrow);

        // backward-direction single step at t=T-1, h0=0 (gh = b_hh)
        const float* wihB = Wih + wih_stride;
        const float* biB  = bih + 24;
        const float* bhB  = bhh + 24;
        u64 ar = pk2(KRZ * (biB[u]     + bhB[u]),     0.0f);
        u64 az = pk2(KRZ * (biB[u + 8] + bhB[u + 8]), 0.0f);
        u64 ax = pk2(biB[u + 16], 0.0f);
        const float bnhB = bhB[u + 16];
#pragma unroll
        for (int p = 0; p < IN_PAIRS; p++) {
            u64 xcp = reinterpret_cast<const u64*>(q)[p];
            u64 wrB = pk2(KRZ * wihB[(u     ) * INF + 2 * p], KRZ * wihB[(u     ) * INF + 2 * p + 1]);
            u64 wzB = pk2(KRZ * wihB[(u +  8) * INF + 2 * p], KRZ * wihB[(u +  8) * INF + 2 * p + 1]);
            u64 wnB = pk2(       wihB[(u + 16) * INF + 2 * p],        wihB[(u + 16) * INF + 2 * p + 1]);
            ar = ffma2(wrB, xcp, ar);
            az = ffma2(wzB, xcp, az);
            ax = ffma2(wnB, xcp, ax);
        }
        float r = fmaf(0.5f, tanh_a(hsum(ar)), 0.5f);
        float z = fmaf(0.5f, tanh_a(hsum(az)), 0.5f);
        float nn = tanh_a(fmaf(r, bnhB, hsum(ax)));
        float hb = (1.0f - z) * nn;   // h0 = 0

        // head: lin1 + LeakyReLU(0.2) + lin2 over [h_f ; h_b]
        float mid = l1b[u];
#pragma unroll
        for (int cc = 0; cc < 8; cc++) {
            float hf_c = __shfl_sync(0xffffffffu, h,  cc, 8);
            float hb_c = __shfl_sync(0xffffffffu, hb, cc, 8);
            mid = fmaf(l1w[u * 16 + cc],     hf_c, mid);
            mid = fmaf(l1w[u * 16 + 8 + cc], hb_c, mid);
        }
        float act = (mid >= 0.0f) ? mid : 0.2f * mid;

        float o = l2b[u];
#pragma unroll
        for (int cc = 0; cc < 8; cc++) {
            float a_c = __shfl_sync(0xffffffffu, act, cc, 8);
            o = fmaf(l2w[u * 8 + cc], a_c, o);
        }
        out[(size_t)n * 8 + u] = o;
    }
}

extern "C" void kernel_launch(void* const* d_in, const int* in_sizes, int n_in,
                              void* d_out, int out_size) {
    (void)in_sizes; (void)n_in; (void)out_size;
    const float* raw  = (const float*)d_in[0];
    const float* Wih0 = (const float*)d_in[1];
    const float* Whh0 = (const float*)d_in[2];
    const float* bih0 = (const float*)d_in[3];
    const float* bhh0 = (const float*)d_in[4];
    const float* WihR = (const float*)d_in[5];   // (3, 2, 24, 16)
    const float* WhhR = (const float*)d_in[6];   // (3, 2, 24, 8)
    const float* bihR = (const float*)d_in[7];   // (3, 2, 24)
    const float* bhhR = (const float*)d_in[8];   // (3, 2, 24)
    const float* l1w  = (const float*)d_in[9];
    const float* l1b  = (const float*)d_in[10];
    const float* l2w  = (const float*)d_in[11];
    const float* l2b  = (const float*)d_in[12];
    float* out = (float*)d_out;

    float *bufA, *bufB;
    cudaGetSymbolAddress((void**)&bufA, g_bufA);
    cudaGetSymbolAddress((void**)&bufB, g_bufB);

    const int BLK_FULL = 2 * (NSEQ / 16);   // 1600 blocks (fwd + bwd)
    const int BLK_HEAD = NSEQ / 16;         // 800 blocks (fwd only)
    const int SMEM8  = 4 * 2 * CHUNK_T * 4 * (8 * 4 + 16)  + 4 * 256;   // 13312
    const int SMEM16 = 4 * 2 * CHUNK_T * 4 * (16 * 4 + 16) + 4 * 256;   // 21504

    // Layer 0: raw -> bufA
    gru_layer_kernel<8, true, false><<<BLK_FULL, 128, SMEM8>>>(
        raw, bufA, Wih0, Whh0, bih0, bhh0, 192,
        nullptr, nullptr, nullptr, nullptr, nullptr);

    // Layer 1: bufA -> bufB
    gru_layer_kernel<16, false, false><<<BLK_FULL, 128, SMEM16>>>(
        bufA, bufB, WihR + 0 * 768, WhhR + 0 * 384, bihR + 0 * 48, bhhR + 0 * 48, 384,
        nullptr, nullptr, nullptr, nullptr, nullptr);

    // Layer 2: bufB -> bufA
    gru_layer_kernel<16, false, false><<<BLK_FULL, 128, SMEM16>>>(
        bufB, bufA, WihR + 1 * 768, WhhR + 1 * 384, bihR + 1 * 48, bhhR + 1 * 48, 384,
        nullptr, nullptr, nullptr, nullptr, nullptr);

    // Layer 3 + head: bufA -> out
    gru_layer_kernel<16, false, true><<<BLK_HEAD, 128, SMEM16>>>(
        bufA, nullptr, WihR + 2 * 768, WhhR + 2 * 384, bihR + 2 * 48, bhhR + 2 * 48, 384,
        l1w, l1b, l2w, l2b, out);
}

// round 9
// speedup vs baseline: 1.4560x; 1.4560x over previous
#include <cuda_runtime.h>

#define NSEQ 12800
#define TSTEPS 512
#define CHUNK_T 8
#define NCHUNK (TSTEPS / CHUNK_T)

typedef unsigned long long u64;

// ---------- packed f32x2 + fast-math helpers ----------
__device__ __forceinline__ u64 pk2(float lo, float hi) {
    u64 u; asm("mov.b64 %0, {%1,%2};" : "=l"(u) : "f"(lo), "f"(hi)); return u;
}
__device__ __forceinline__ float2 upk2(u64 u) {
    float2 v; asm("mov.b64 {%0,%1}, %2;" : "=f"(v.x), "=f"(v.y) : "l"(u)); return v;
}
__device__ __forceinline__ u64 ffma2(u64 a, u64 b, u64 c) {
    u64 d; asm("fma.rn.f32x2 %0, %1, %2, %3;" : "=l"(d) : "l"(a), "l"(b), "l"(c)); return d;
}
__device__ __forceinline__ float tanh_a(float x) {
    float r; asm("tanh.approx.f32 %0, %1;" : "=f"(r) : "f"(x)); return r;
}
__device__ __forceinline__ float hsum(u64 a) { float2 v = upk2(a); return v.x + v.y; }

// r/z gate weights pre-scaled by 0.5: sigmoid(x) = 0.5*tanh(x/2) + 0.5  (1 MUFU)
#define KRZ (0.5f)

// ---------- global scratch: ping-pong activation buffers, layout (T, N, 16) ----------
__device__ float g_bufA[(size_t)TSTEPS * NSEQ * 16];
__device__ float g_bufB[(size_t)TSTEPS * NSEQ * 16];

// ---------- per-WARP cp.async chunk loader (no block barriers anywhere) ----------
// warp-private chunk layout: [tt (CHUNK_T)][scan (4)][INF floats + 16B pad]
// lane-constant decomposition: scan/c16 fixed per lane; only tt advances ->
// strength-reduced pointer increments, no div/mod temps in the hot loop.
template <int INF, bool RAW>
__device__ __forceinline__ void issue_chunk_w(char* dst, const float* __restrict__ x_in,
                                              int n0, int c, int dir, int lane) {
    constexpr int VPS = INF / 4;                 // 16B vectors per scan row
    constexpr int ROW_B = INF * 4 + 16;
    constexpr int TT_B = 4 * ROW_B;
    constexpr int PER_TT = 4 * VPS;              // lanes covering one tt
    constexpr int TT_PER_K = 32 / PER_TT;        // tt advance per iteration
    const int tt0  = lane / PER_TT;
    const int scan = (lane % PER_TT) / VPS;
    const int c16  = lane % VPS;
    const int t00 = dir ? (TSTEPS - 1 - c * CHUNK_T - tt0) : (c * CHUNK_T + tt0);
    const float* g = RAW
        ? x_in + (size_t)(n0 + scan) * 4096 + (size_t)t00 * 8 + c16 * 4
        : x_in + ((size_t)t00 * NSEQ + (size_t)(n0 + scan)) * 16 + c16 * 4;
    const ptrdiff_t gstep = (RAW ? (ptrdiff_t)8 : (ptrdiff_t)NSEQ * 16)
                          * (dir ? -TT_PER_K : TT_PER_K);
    unsigned s = (unsigned)__cvta_generic_to_shared(dst + tt0 * TT_B + scan * ROW_B + c16 * 16);
#pragma unroll
    for (int k = 0; k < CHUNK_T / TT_PER_K; k++) {
        asm volatile("cp.async.cg.shared.global [%0], [%1], 16;" :: "r"(s), "l"(g));
        s += TT_PER_K * TT_B;
        g += gstep;
    }
}

// One bidirectional-GRU layer. Each WARP owns 4 scans of one direction and
// free-runs: private double-buffered cp.async x-ring, no __syncthreads, so
// warps de-phase and interleave each other's dependency chains.
// 8 lanes per scan; lane u owns hidden unit u (gate rows u, u+8, u+16).
// All weights in registers; h broadcast via 8 shfl. HEAD (layer 3): fwd only,
// no stores; fused 1-step bwd GRU at t=T-1 (h0=0) + lin1/LeakyReLU/lin2 head.
template <int INF, bool RAW_IN, bool HEAD, int MINB>
__global__ void __launch_bounds__(128, MINB)
gru_layer_kernel(const float* __restrict__ x_in, float* __restrict__ x_out,
                 const float* __restrict__ Wih, const float* __restrict__ Whh,
                 const float* __restrict__ bih, const float* __restrict__ bhh,
                 int wih_stride,
                 const float* __restrict__ l1w, const float* __restrict__ l1b,
                 const float* __restrict__ l2w, const float* __restrict__ l2b,
                 float* __restrict__ out)
{
    constexpr int IN_PAIRS = INF / 2;
    constexpr int ROW_B = INF * 4 + 16;
    constexpr int TT_B = 4 * ROW_B;
    constexpr int CHUNK_B = CHUNK_T * TT_B;
    constexpr int WARP_B = 2 * CHUNK_B;

    extern __shared__ char sb[];

    const int tid = threadIdx.x;
    const int wid = tid >> 5;
    const int lane = tid & 31;
    const int u = tid & 7;
    const int sg = (tid >> 3) & 3;               // scan within warp
    const int warpG = blockIdx.x * 4 + wid;
    const int dir = HEAD ? 0 : (warpG / (NSEQ / 4));
    const int wi  = HEAD ? warpG : (warpG % (NSEQ / 4));
    const int n0 = wi * 4;
    const int n = n0 + sg;
    char* wsb = sb + wid * WARP_B;               // this warp's private ring

    // ---- register weights, pre-scaled ----
    const float* wih = Wih + dir * wih_stride;
    const float* whh = Whh + dir * 192;
    const float* bi  = bih + dir * 24;
    const float* bh  = bhh + dir * 24;

    u64 wr[IN_PAIRS], wz[IN_PAIRS], wn[IN_PAIRS];
#pragma unroll
    for (int p = 0; p < IN_PAIRS; p++) {
        wr[p] = pk2(KRZ * wih[(u     ) * INF + 2 * p], KRZ * wih[(u     ) * INF + 2 * p + 1]);
        wz[p] = pk2(KRZ * wih[(u +  8) * INF + 2 * p], KRZ * wih[(u +  8) * INF + 2 * p + 1]);
        wn[p] = pk2(       wih[(u + 16) * INF + 2 * p],        wih[(u + 16) * INF + 2 * p + 1]);
    }
    u64 ur[4], uz[4], un[4];
#pragma unroll
    for (int p = 0; p < 4; p++) {
        ur[p] = pk2(KRZ * whh[(u     ) * 8 + 2 * p], KRZ * whh[(u     ) * 8 + 2 * p + 1]);
        uz[p] = pk2(KRZ * whh[(u +  8) * 8 + 2 * p], KRZ * whh[(u +  8) * 8 + 2 * p + 1]);
        un[p] = pk2(       whh[(u + 16) * 8 + 2 * p],        whh[(u + 16) * 8 + 2 * p + 1]);
    }
    const u64 brp  = pk2(KRZ * (bi[u]     + bh[u]),     0.0f);
    const u64 bzp  = pk2(KRZ * (bi[u + 8] + bh[u + 8]), 0.0f);
    const u64 bnxp = pk2(bi[u + 16], 0.0f);
    const u64 bnhp = pk2(bh[u + 16], 0.0f);

    const int t0 = dir ? (TSTEPS - 1) : 0;
    float* op = HEAD ? nullptr
                     : (x_out + ((size_t)t0 * NSEQ + (size_t)n) * 16 + dir * 8 + u);
    const ptrdiff_t ostep = (ptrdiff_t)NSEQ * 16 * (dir ? -1 : 1);

    // ---- prime the per-warp pipeline ----
    issue_chunk_w<INF, RAW_IN>(wsb, x_in, n0, 0, dir, lane);
    asm volatile("cp.async.commit_group;" ::: "memory");
    issue_chunk_w<INF, RAW_IN>(wsb + CHUNK_B, x_in, n0, 1, dir, lane);
    asm volatile("cp.async.commit_group;" ::: "memory");

    float h = 0.0f;

#pragma unroll 1
    for (int c = 0; c < NCHUNK; c++) {
        asm volatile("cp.async.wait_group 1;" ::: "memory");
        __syncwarp();
        const char* xbase = wsb + (c & 1) * CHUNK_B + sg * ROW_B;

#pragma unroll
        for (int tt = 0; tt < CHUNK_T; tt++) {
            const ulonglong2* q = reinterpret_cast<const ulonglong2*>(xbase + tt * TT_B);

            // broadcast h[0..7] of this scan group first (cover shfl latency
            // with the independent x-projection below)
            u64 hp[4];
#pragma unroll
            for (int p = 0; p < 4; p++) {
                float lo = __shfl_sync(0xffffffffu, h, 2 * p,     8);
                float hi = __shfl_sync(0xffffffffu, h, 2 * p + 1, 8);
                hp[p] = pk2(lo, hi);
            }

            u64 ar = brp, az = bzp, axn = bnxp, ahn = bnhp;
            // x-projection in blocks of 4 pairs (limits xc register footprint)
#pragma unroll
            for (int blk = 0; blk < IN_PAIRS / 4; blk++) {
                ulonglong2 va = q[2 * blk];
                ulonglong2 vb = q[2 * blk + 1];
                ar  = ffma2(wr[4 * blk + 0], va.x, ar);
                az  = ffma2(wz[4 * blk + 0], va.x, az);
                axn = ffma2(wn[4 * blk + 0], va.x, axn);
                ar  = ffma2(wr[4 * blk + 1], va.y, ar);
                az  = ffma2(wz[4 * blk + 1], va.y, az);
                axn = ffma2(wn[4 * blk + 1], va.y, axn);
                ar  = ffma2(wr[4 * blk + 2], vb.x, ar);
                az  = ffma2(wz[4 * blk + 2], vb.x, az);
                axn = ffma2(wn[4 * blk + 2], vb.x, axn);
                ar  = ffma2(wr[4 * blk + 3], vb.y, ar);
                az  = ffma2(wz[4 * blk + 3], vb.y, az);
                axn = ffma2(wn[4 * blk + 3], vb.y, axn);
            }
            // h-recurrence
#pragma unroll
            for (int p = 0; p < 4; p++) {
                ar  = ffma2(ur[p], hp[p], ar);
                az  = ffma2(uz[p], hp[p], az);
                ahn = ffma2(un[p], hp[p], ahn);
            }
            float r = fmaf(0.5f, tanh_a(hsum(ar)), 0.5f);   // sigmoid
            float z = fmaf(0.5f, tanh_a(hsum(az)), 0.5f);   // sigmoid
            float nn = tanh_a(fmaf(r, hsum(ahn), hsum(axn)));
            h = fmaf(z, h - nn, nn);

            if (!HEAD) { *op = h; op += ostep; }
        }
        // refill the buffer this warp just finished consuming (warp-sequential,
        // no cross-warp sharing -> no block barrier needed)
        if (c + 2 < NCHUNK)
            issue_chunk_w<INF, RAW_IN>(wsb + (c & 1) * CHUNK_B, x_in, n0, c + 2, dir, lane);
        asm volatile("cp.async.commit_group;" ::: "memory");
    }

    if (HEAD) {
        // x[T-1] still resident in the last chunk's buffer
        const char* xrow = wsb + ((NCHUNK - 1) & 1) * CHUNK_B
                         + sg * ROW_B + (CHUNK_T - 1) * TT_B;
        const ulonglong2* q = reinterpret_cast<const ulonglong2*>(xrow);

        // backward-direction single step at t=T-1, h0=0 (gh = b_hh)
        const float* wihB = Wih + wih_stride;
        const float* biB  = bih + 24;
        const float* bhB  = bhh + 24;
        u64 ar = pk2(KRZ * (biB[u]     + bhB[u]),     0.0f);
        u64 az = pk2(KRZ * (biB[u + 8] + bhB[u + 8]), 0.0f);
        u64 ax = pk2(biB[u + 16], 0.0f);
        const float bnhB = bhB[u + 16];
#pragma unroll
        for (int p = 0; p < IN_PAIRS; p++) {
            u64 xcp = reinterpret_cast<const u64*>(q)[p];
            u64 wrB = pk2(KRZ * wihB[(u     ) * INF + 2 * p], KRZ * wihB[(u     ) * INF + 2 * p + 1]);
            u64 wzB = pk2(KRZ * wihB[(u +  8) * INF + 2 * p], KRZ * wihB[(u +  8) * INF + 2 * p + 1]);
            u64 wnB = pk2(       wihB[(u + 16) * INF + 2 * p],        wihB[(u + 16) * INF + 2 * p + 1]);
            ar = ffma2(wrB, xcp, ar);
            az = ffma2(wzB, xcp, az);
            ax = ffma2(wnB, xcp, ax);
        }
        float r = fmaf(0.5f, tanh_a(hsum(ar)), 0.5f);
        float z = fmaf(0.5f, tanh_a(hsum(az)), 0.5f);
        float nn = tanh_a(fmaf(r, bnhB, hsum(ax)));
        float hb = (1.0f - z) * nn;   // h0 = 0

        // head: lin1 + LeakyReLU(0.2) + lin2 over [h_f ; h_b]
        float mid = l1b[u];
#pragma unroll
        for (int cc = 0; cc < 8; cc++) {
            float hf_c = __shfl_sync(0xffffffffu, h,  cc, 8);
            float hb_c = __shfl_sync(0xffffffffu, hb, cc, 8);
            mid = fmaf(l1w[u * 16 + cc],     hf_c, mid);
            mid = fmaf(l1w[u * 16 + 8 + cc], hb_c, mid);
        }
        float act = (mid >= 0.0f) ? mid : 0.2f * mid;

        float o = l2b[u];
#pragma unroll
        for (int cc = 0; cc < 8; cc++) {
            float a_c = __shfl_sync(0xffffffffu, act, cc, 8);
            o = fmaf(l2w[u * 8 + cc], a_c, o);
        }
        out[(size_t)n * 8 + u] = o;
    }
}

extern "C" void kernel_launch(void* const* d_in, const int* in_sizes, int n_in,
                              void* d_out, int out_size) {
    (void)in_sizes; (void)n_in; (void)out_size;
    const float* raw  = (const float*)d_in[0];
    const float* Wih0 = (const float*)d_in[1];
    const float* Whh0 = (const float*)d_in[2];
    const float* bih0 = (const float*)d_in[3];
    const float* bhh0 = (const float*)d_in[4];
    const float* WihR = (const float*)d_in[5];   // (3, 2, 24, 16)
    const float* WhhR = (const float*)d_in[6];   // (3, 2, 24, 8)
    const float* bihR = (const float*)d_in[7];   // (3, 2, 24)
    const float* bhhR = (const float*)d_in[8];   // (3, 2, 24)
    const float* l1w  = (const float*)d_in[9];
    const float* l1b  = (const float*)d_in[10];
    const float* l2w  = (const float*)d_in[11];
    const float* l2b  = (const float*)d_in[12];
    float* out = (float*)d_out;

    float *bufA, *bufB;
    cudaGetSymbolAddress((void**)&bufA, g_bufA);
    cudaGetSymbolAddress((void**)&bufB, g_bufB);

    const int BLK_FULL = 2 * (NSEQ / 16);   // 1600 blocks (fwd + bwd)
    const int BLK_HEAD = NSEQ / 16;         // 800 blocks (fwd only)
    const int SMEM8  = 4 * 2 * CHUNK_T * 4 * (8 * 4 + 16);    // 12288
    const int SMEM16 = 4 * 2 * CHUNK_T * 4 * (16 * 4 + 16);   // 20480

    // Layer 0: raw -> bufA  (small weight set -> 6 blocks/SM)
    gru_layer_kernel<8, true, false, 6><<<BLK_FULL, 128, SMEM8>>>(
        raw, bufA, Wih0, Whh0, bih0, bhh0, 192,
        nullptr, nullptr, nullptr, nullptr, nullptr);

    // Layer 1: bufA -> bufB  (5 blocks/SM target)
    gru_layer_kernel<16, false, false, 5><<<BLK_FULL, 128, SMEM16>>>(
        bufA, bufB, WihR + 0 * 768, WhhR + 0 * 384, bihR + 0 * 48, bhhR + 0 * 48, 384,
        nullptr, nullptr, nullptr, nullptr, nullptr);

    // Layer 2: bufB -> bufA
    gru_layer_kernel<16, false, false, 5><<<BLK_FULL, 128, SMEM16>>>(
        bufB, bufA, WihR + 1 * 768, WhhR + 1 * 384, bihR + 1 * 48, bhhR + 1 * 48, 384,
        nullptr, nullptr, nullptr, nullptr, nullptr);

    // Layer 3 + head: bufA -> out
    gru_layer_kernel<16, false, true, 5><<<BLK_HEAD, 128, SMEM16>>>(
        bufA, nullptr, WihR + 2 * 768, WhhR + 2 * 384, bihR + 2 * 48, bhhR + 2 * 48, 384,
        l1w, l1b, l2w, l2b, out);
}

// round 10
// speedup vs baseline: 1.6800x; 1.1539x over previous
#include <cuda_runtime.h>

#define NSEQ 12800
#define TSTEPS 512
#define CHUNK_T 8
#define NCHUNK (TSTEPS / CHUNK_T)

typedef unsigned long long u64;

// ---------- packed f32x2 + fast-math helpers ----------
__device__ __forceinline__ u64 pk2(float lo, float hi) {
    u64 u; asm("mov.b64 %0, {%1,%2};" : "=l"(u) : "f"(lo), "f"(hi)); return u;
}
__device__ __forceinline__ float2 upk2(u64 u) {
    float2 v; asm("mov.b64 {%0,%1}, %2;" : "=f"(v.x), "=f"(v.y) : "l"(u)); return v;
}
__device__ __forceinline__ u64 ffma2(u64 a, u64 b, u64 c) {
    u64 d; asm("fma.rn.f32x2 %0, %1, %2, %3;" : "=l"(d) : "l"(a), "l"(b), "l"(c)); return d;
}
__device__ __forceinline__ float tanh_a(float x) {
    float r; asm("tanh.approx.f32 %0, %1;" : "=f"(r) : "f"(x)); return r;
}
__device__ __forceinline__ float hsum(u64 a) { float2 v = upk2(a); return v.x + v.y; }

// r/z gate weights pre-scaled by 0.5: sigmoid(x) = 0.5*tanh(x/2) + 0.5  (1 MUFU)
#define KRZ (0.5f)

// ---------- global scratch: ping-pong activation buffers, layout (T, N, 16) ----------
__device__ float g_bufA[(size_t)TSTEPS * NSEQ * 16];
__device__ float g_bufB[(size_t)TSTEPS * NSEQ * 16];

// ---------- per-WARP cp.async chunk loader (no block barriers anywhere) ----------
// warp-private chunk layout: [tt (CHUNK_T)][scan (4)][INF floats + 16B pad]
template <int INF, bool RAW>
__device__ __forceinline__ void issue_chunk_w(char* dst, const float* __restrict__ x_in,
                                              int n0, int c, int dir, int lane) {
    constexpr int VPS = INF / 4;                 // 16B vectors per scan row
    constexpr int ROW_B = INF * 4 + 16;
    constexpr int TT_B = 4 * ROW_B;
    constexpr int PER_TT = 4 * VPS;              // lanes covering one tt
    constexpr int TT_PER_K = 32 / PER_TT;        // tt advance per iteration
    const int tt0  = lane / PER_TT;
    const int scan = (lane % PER_TT) / VPS;
    const int c16  = lane % VPS;
    const int t00 = dir ? (TSTEPS - 1 - c * CHUNK_T - tt0) : (c * CHUNK_T + tt0);
    const float* g = RAW
        ? x_in + (size_t)(n0 + scan) * 4096 + (size_t)t00 * 8 + c16 * 4
        : x_in + ((size_t)t00 * NSEQ + (size_t)(n0 + scan)) * 16 + c16 * 4;
    const ptrdiff_t gstep = (RAW ? (ptrdiff_t)8 : (ptrdiff_t)NSEQ * 16)
                          * (dir ? -TT_PER_K : TT_PER_K);
    unsigned s = (unsigned)__cvta_generic_to_shared(dst + tt0 * TT_B + scan * ROW_B + c16 * 16);
#pragma unroll
    for (int k = 0; k < CHUNK_T / TT_PER_K; k++) {
        asm volatile("cp.async.cg.shared.global [%0], [%1], 16;" :: "r"(s), "l"(g));
        s += TT_PER_K * TT_B;
        g += gstep;
    }
}

// One bidirectional-GRU layer. Each WARP owns 4 scans of one direction and
// free-runs (private double-buffered cp.async x-ring, no __syncthreads).
// 8 lanes per scan; lane u owns hidden unit u (gate rows u, u+8, u+16).
// SOFTWARE PIPELINE: step t+1's x-projection (independent of h_t) is
// accumulated during step t's shfl/tanh dependency chain, keeping the fma
// pipe busy through the recurrence latency. All weights in registers.
// HEAD (layer 3): fwd only, no stores; fused 1-step bwd GRU at t=T-1 (h0=0)
// + lin1/LeakyReLU(0.2)/lin2 head.
template <int INF, bool RAW_IN, bool HEAD, int MINB>
__global__ void __launch_bounds__(128, MINB)
gru_layer_kernel(const float* __restrict__ x_in, float* __restrict__ x_out,
                 const float* __restrict__ Wih, const float* __restrict__ Whh,
                 const float* __restrict__ bih, const float* __restrict__ bhh,
                 int wih_stride,
                 const float* __restrict__ l1w, const float* __restrict__ l1b,
                 const float* __restrict__ l2w, const float* __restrict__ l2b,
                 float* __restrict__ out)
{
    constexpr int IN_PAIRS = INF / 2;
    constexpr int ROW_B = INF * 4 + 16;
    constexpr int TT_B = 4 * ROW_B;
    constexpr int CHUNK_B = CHUNK_T * TT_B;
    constexpr int WARP_B = 2 * CHUNK_B;

    extern __shared__ char sb[];

    const int tid = threadIdx.x;
    const int wid = tid >> 5;
    const int lane = tid & 31;
    const int u = tid & 7;
    const int sg = (tid >> 3) & 3;               // scan within warp
    const int warpG = blockIdx.x * 4 + wid;
    const int dir = HEAD ? 0 : (warpG / (NSEQ / 4));
    const int wi  = HEAD ? warpG : (warpG % (NSEQ / 4));
    const int n0 = wi * 4;
    const int n = n0 + sg;
    char* wsb = sb + wid * WARP_B;               // this warp's private ring

    // ---- register weights, pre-scaled ----
    const float* wih = Wih + dir * wih_stride;
    const float* whh = Whh + dir * 192;
    const float* bi  = bih + dir * 24;
    const float* bh  = bhh + dir * 24;

    u64 wr[IN_PAIRS], wz[IN_PAIRS], wn[IN_PAIRS];
#pragma unroll
    for (int p = 0; p < IN_PAIRS; p++) {
        wr[p] = pk2(KRZ * wih[(u     ) * INF + 2 * p], KRZ * wih[(u     ) * INF + 2 * p + 1]);
        wz[p] = pk2(KRZ * wih[(u +  8) * INF + 2 * p], KRZ * wih[(u +  8) * INF + 2 * p + 1]);
        wn[p] = pk2(       wih[(u + 16) * INF + 2 * p],        wih[(u + 16) * INF + 2 * p + 1]);
    }
    u64 ur[4], uz[4], un[4];
#pragma unroll
    for (int p = 0; p < 4; p++) {
        ur[p] = pk2(KRZ * whh[(u     ) * 8 + 2 * p], KRZ * whh[(u     ) * 8 + 2 * p + 1]);
        uz[p] = pk2(KRZ * whh[(u +  8) * 8 + 2 * p], KRZ * whh[(u +  8) * 8 + 2 * p + 1]);
        un[p] = pk2(       whh[(u + 16) * 8 + 2 * p],        whh[(u + 16) * 8 + 2 * p + 1]);
    }
    const u64 brp  = pk2(KRZ * (bi[u]     + bh[u]),     0.0f);
    const u64 bzp  = pk2(KRZ * (bi[u + 8] + bh[u + 8]), 0.0f);
    const u64 bnxp = pk2(bi[u + 16], 0.0f);
    const u64 bnhp = pk2(bh[u + 16], 0.0f);

    const int t0 = dir ? (TSTEPS - 1) : 0;
    float* op = HEAD ? nullptr
                     : (x_out + ((size_t)t0 * NSEQ + (size_t)n) * 16 + dir * 8 + u);
    const ptrdiff_t ostep = (ptrdiff_t)NSEQ * 16 * (dir ? -1 : 1);

    // pipelined x-projection accumulators (carry bias + x·W for the NEXT step)
    u64 ar, az, axn;
    auto accum_x = [&](const char* qp) {
        const ulonglong2* q = reinterpret_cast<const ulonglong2*>(qp);
        ar = brp; az = bzp; axn = bnxp;
#pragma unroll
        for (int blk = 0; blk < IN_PAIRS / 4; blk++) {
            ulonglong2 va = q[2 * blk];
            ulonglong2 vb = q[2 * blk + 1];
            ar  = ffma2(wr[4 * blk + 0], va.x, ar);
            az  = ffma2(wz[4 * blk + 0], va.x, az);
            axn = ffma2(wn[4 * blk + 0], va.x, axn);
            ar  = ffma2(wr[4 * blk + 1], va.y, ar);
            az  = ffma2(wz[4 * blk + 1], va.y, az);
            axn = ffma2(wn[4 * blk + 1], va.y, axn);
            ar  = ffma2(wr[4 * blk + 2], vb.x, ar);
            az  = ffma2(wz[4 * blk + 2], vb.x, az);
            axn = ffma2(wn[4 * blk + 2], vb.x, axn);
            ar  = ffma2(wr[4 * blk + 3], vb.y, ar);
            az  = ffma2(wz[4 * blk + 3], vb.y, az);
            axn = ffma2(wn[4 * blk + 3], vb.y, axn);
        }
    };

    // ---- prime: two chunks in flight, then preaccumulate step 0 ----
    issue_chunk_w<INF, RAW_IN>(wsb, x_in, n0, 0, dir, lane);
    asm volatile("cp.async.commit_group;" ::: "memory");
    issue_chunk_w<INF, RAW_IN>(wsb + CHUNK_B, x_in, n0, 1, dir, lane);
    asm volatile("cp.async.commit_group;" ::: "memory");
    asm volatile("cp.async.wait_group 1;" ::: "memory");
    __syncwarp();

    float h = 0.0f;
    accum_x(wsb + sg * ROW_B);     // chunk 0, tt 0

#pragma unroll 1
    for (int c = 0; c < NCHUNK; c++) {
        const char* xbase = wsb + (c & 1) * CHUNK_B + sg * ROW_B;

#pragma unroll
        for (int tt = 0; tt < CHUNK_T; tt++) {
            // h broadcast, consumed pair-by-pair (keeps 1 hp pair live)
            u64 ahn = bnhp;
#pragma unroll
            for (int p = 0; p < 4; p++) {
                float lo = __shfl_sync(0xffffffffu, h, 2 * p,     8);
                float hi = __shfl_sync(0xffffffffu, h, 2 * p + 1, 8);
                u64 hp = pk2(lo, hi);
                ar  = ffma2(ur[p], hp, ar);
                az  = ffma2(uz[p], hp, az);
                ahn = ffma2(un[p], hp, ahn);
            }
            // snapshot gate sums, then recycle accumulators for step t+1's x
            float sr = hsum(ar), sz = hsum(az);
            float sxn = hsum(axn), shn = hsum(ahn);
            if (tt < CHUNK_T - 1)
                accum_x(xbase + (tt + 1) * TT_B);   // overlaps the tanh chain

            float r = fmaf(0.5f, tanh_a(sr), 0.5f);   // sigmoid
            float z = fmaf(0.5f, tanh_a(sz), 0.5f);   // sigmoid
            float nn = tanh_a(fmaf(r, shn, sxn));
            h = fmaf(z, h - nn, nn);

            if (!HEAD) { *op = h; op += ostep; }
        }
        // refill the buffer just consumed, then wait for the next chunk and
        // preaccumulate its first step
        if (c + 2 < NCHUNK)
            issue_chunk_w<INF, RAW_IN>(wsb + (c & 1) * CHUNK_B, x_in, n0, c + 2, dir, lane);
        asm volatile("cp.async.commit_group;" ::: "memory");
        if (c + 1 < NCHUNK) {
            asm volatile("cp.async.wait_group 1;" ::: "memory");
            __syncwarp();
            accum_x(wsb + ((c + 1) & 1) * CHUNK_B + sg * ROW_B);
        }
    }

    if (HEAD) {
        // x[T-1] still resident in the last chunk's buffer
        const char* xrow = wsb + ((NCHUNK - 1) & 1) * CHUNK_B
                         + sg * ROW_B + (CHUNK_T - 1) * TT_B;
        const u64* q = reinterpret_cast<const u64*>(xrow);

        // backward-direction single step at t=T-1, h0=0 (gh = b_hh)
        const float* wihB = Wih + wih_stride;
        const float* biB  = bih + 24;
        const float* bhB  = bhh + 24;
        u64 br2 = pk2(KRZ * (biB[u]     + bhB[u]),     0.0f);
        u64 bz2 = pk2(KRZ * (biB[u + 8] + bhB[u + 8]), 0.0f);
        u64 bx2 = pk2(biB[u + 16], 0.0f);
        const float bnhB = bhB[u + 16];
#pragma unroll
        for (int p = 0; p < IN_PAIRS; p++) {
            u64 xcp = q[p];
            u64 wrB = pk2(KRZ * wihB[(u     ) * INF + 2 * p], KRZ * wihB[(u     ) * INF + 2 * p + 1]);
            u64 wzB = pk2(KRZ * wihB[(u +  8) * INF + 2 * p], KRZ * wihB[(u +  8) * INF + 2 * p + 1]);
            u64 wnB = pk2(       wihB[(u + 16) * INF + 2 * p],        wihB[(u + 16) * INF + 2 * p + 1]);
            br2 = ffma2(wrB, xcp, br2);
            bz2 = ffma2(wzB, xcp, bz2);
            bx2 = ffma2(wnB, xcp, bx2);
        }
        float r = fmaf(0.5f, tanh_a(hsum(br2)), 0.5f);
        float z = fmaf(0.5f, tanh_a(hsum(bz2)), 0.5f);
        float nn = tanh_a(fmaf(r, bnhB, hsum(bx2)));
        float hb = (1.0f - z) * nn;   // h0 = 0

        // head: lin1 + LeakyReLU(0.2) + lin2 over [h_f ; h_b]
        float mid = l1b[u];
#pragma unroll
        for (int cc = 0; cc < 8; cc++) {
            float hf_c = __shfl_sync(0xffffffffu, h,  cc, 8);
            float hb_c = __shfl_sync(0xffffffffu, hb, cc, 8);
            mid = fmaf(l1w[u * 16 + cc],     hf_c, mid);
            mid = fmaf(l1w[u * 16 + 8 + cc], hb_c, mid);
        }
        float act = (mid >= 0.0f) ? mid : 0.2f * mid;

        float o = l2b[u];
#pragma unroll
        for (int cc = 0; cc < 8; cc++) {
            float a_c = __shfl_sync(0xffffffffu, act, cc, 8);
            o = fmaf(l2w[u * 8 + cc], a_c, o);
        }
        out[(size_t)n * 8 + u] = o;
    }
}

extern "C" void kernel_launch(void* const* d_in, const int* in_sizes, int n_in,
                              void* d_out, int out_size) {
    (void)in_sizes; (void)n_in; (void)out_size;
    const float* raw  = (const float*)d_in[0];
    const float* Wih0 = (const float*)d_in[1];
    const float* Whh0 = (const float*)d_in[2];
    const float* bih0 = (const float*)d_in[3];
    const float* bhh0 = (const float*)d_in[4];
    const float* WihR = (const float*)d_in[5];   // (3, 2, 24, 16)
    const float* WhhR = (const float*)d_in[6];   // (3, 2, 24, 8)
    const float* bihR = (const float*)d_in[7];   // (3, 2, 24)
    const float* bhhR = (const float*)d_in[8];   // (3, 2, 24)
    const float* l1w  = (const float*)d_in[9];
    const float* l1b  = (const float*)d_in[10];
    const float* l2w  = (const float*)d_in[11];
    const float* l2b  = (const float*)d_in[12];
    float* out = (float*)d_out;

    float *bufA, *bufB;
    cudaGetSymbolAddress((void**)&bufA, g_bufA);
    cudaGetSymbolAddress((void**)&bufB, g_bufB);

    const int BLK_FULL = 2 * (NSEQ / 16);   // 1600 blocks (fwd + bwd)
    const int BLK_HEAD = NSEQ / 16;         // 800 blocks (fwd only)
    const int SMEM8  = 4 * 2 * CHUNK_T * 4 * (8 * 4 + 16);    // 12288
    const int SMEM16 = 4 * 2 * CHUNK_T * 4 * (16 * 4 + 16);   // 20480

    // Layer 0: raw -> bufA  (half-size weight set: 5 blocks/SM, no spills)
    gru_layer_kernel<8, true, false, 5><<<BLK_FULL, 128, SMEM8>>>(
        raw, bufA, Wih0, Whh0, bih0, bhh0, 192,
        nullptr, nullptr, nullptr, nullptr, nullptr);

    // Layer 1: bufA -> bufB
    gru_layer_kernel<16, false, false, 4><<<BLK_FULL, 128, SMEM16>>>(
        bufA, bufB, WihR + 0 * 768, WhhR + 0 * 384, bihR + 0 * 48, bhhR + 0 * 48, 384,
        nullptr, nullptr, nullptr, nullptr, nullptr);

    // Layer 2: bufB -> bufA
    gru_layer_kernel<16, false, false, 4><<<BLK_FULL, 128, SMEM16>>>(
        bufB, bufA, WihR + 1 * 768, WhhR + 1 * 384, bihR + 1 * 48, bhhR + 1 * 48, 384,
        nullptr, nullptr, nullptr, nullptr, nullptr);

    // Layer 3 + head: bufA -> out
    gru_layer_kernel<16, false, true, 4><<<BLK_HEAD, 128, SMEM16>>>(
        bufA, nullptr, WihR + 2 * 768, WhhR + 2 * 384, bihR + 2 * 48, bhhR + 2 * 48, 384,
        l1w, l1b, l2w, l2b, out);
}